// round 14
// baseline (speedup 1.0000x reference)
#include <cuda_runtime.h>

// ---------------- problem constants ----------------
#define NPC   16
#define FBP   8
#define CH    128
#define HH    96
#define H0    94          // after piece conv
#define H1    92          // after conv #1
#define H2    90          // after conv #2
#define FEAT  (CH*H2*H2)  // 1,036,800
#define OUTD  256
#define GCHUNK 4096
#define NBLK  ((FEAT + GCHUNK - 1) / GCHUNK)   // 254

typedef unsigned long long ull;

// ---------------- scratch (no allocation allowed) ----------------
__device__ float g_y0[CH * H0 * H0];
__device__ float g_y1[CH * H1 * H1];
__device__ float g_y2[CH * H2 * H2];
__device__ float g_part[NBLK * OUTD];

// ---------------- packed f32x2 helpers (sm_103a) ----------------
__device__ __forceinline__ ull pk(float lo, float hi) {
    ull r;
    asm("mov.b64 %0, {%1, %2};" : "=l"(r) : "f"(lo), "f"(hi));
    return r;
}
__device__ __forceinline__ void fma2(ull &d, ull a, ull b) {
    asm("fma.rn.f32x2 %0, %1, %2, %0;" : "+l"(d) : "l"(a), "l"(b));
}
__device__ __forceinline__ float2 up(ull v) {
    float x, y;
    asm("mov.b64 {%0, %1}, %2;" : "=f"(x), "=f"(y) : "l"(v));
    return make_float2(x, y);
}

// ---------------- kernel 1: grouped piece conv + bias + relu ----------------
__global__ void piece_conv(const int* __restrict__ x, const float* __restrict__ cw,
                           const float* __restrict__ cb, float* __restrict__ y0) {
    __shared__ float sw[72];
    __shared__ float sb[8];
    int p = blockIdx.y;
    if (threadIdx.x < 72) sw[threadIdx.x] = cw[p * 72 + threadIdx.x];
    if (threadIdx.x < 8)  sb[threadIdx.x] = cb[p * 8 + threadIdx.x];
    __syncthreads();
    int pix = blockIdx.x * blockDim.x + threadIdx.x;
    if (pix >= H0 * H0) return;
    int i = pix / H0, j = pix % H0;
    float acc[FBP];
#pragma unroll
    for (int f = 0; f < FBP; f++) acc[f] = sb[f];
#pragma unroll
    for (int di = 0; di < 3; di++) {
#pragma unroll
        for (int dj = 0; dj < 3; dj++) {
            int v = x[(i + di) * HH + (j + dj)];
            if (v == p) {
#pragma unroll
                for (int f = 0; f < FBP; f++) acc[f] += sw[f * 9 + di * 3 + dj];
            }
        }
    }
#pragma unroll
    for (int f = 0; f < FBP; f++)
        y0[(p * FBP + f) * (H0 * H0) + pix] = fmaxf(acc[f], 0.f);
}

// ---------------- conv 3x3 VALID + bias + relu ----------------
// 128 threads/block, 64 Cout per block (z selects half), tile 4 rows x 16 cols.
// Thread = 2 Cout x 1 rowpair x 8 col-f32x2 (32 acc regs).
// Each weight LDS.64 feeds 8 FMA2; each (ci,di) x read = 5 LDS.128 feeds 48.
// Double-buffered SMEM, one __syncthreads per cib iteration; register
// prefetch of tile i+2 flies under the FMA2 phase.
// Launch with z=2 (276 blocks, ~2/SM) so staging latency is cross-block hidden.
#define CI_T 4
#define NITER (CH / CI_T)   // 32
#define WS_STRIDE 37
__global__ void __launch_bounds__(128, 4) conv3x3(
    const float* __restrict__ in, const float* __restrict__ w,
    const float* __restrict__ b, float* __restrict__ out,
    int Hin, int Hout) {
    __shared__ __align__(16) float2 ws[2][64 * WS_STRIDE];
    __shared__ __align__(16) float2 xp[2][CI_T * 4 * 18];   // 288 entries

    int t = threadIdx.x;
    int cogrp = t >> 2;               // 0..31, 2 Cout each
    int pg    = t & 3;
    int rp    = pg & 1;               // rowpair: rows (rp, rp+2)
    int chh   = pg >> 1;              // col half: cols chh*8 .. +7 (f32x2 units)
    int i0 = blockIdx.y * 4, j0 = blockIdx.x * 16;
    int zc = blockIdx.z * 64;

    // weight staging: thread stages row lc = t>>1, scalars r0..r0+17 (contiguous)
    int lc_s = t >> 1;
    int r0_s = (t & 1) * 18;
    const float* wg_base = w + (size_t)(zc + lc_s) * (CH * 9) + r0_s;
    int wsbase = lc_s * WS_STRIDE + r0_s;

    // x staging maps: 288 entries, thread covers t, t+128, (t<32) t+256
    int xg_off[3], xci_[3];
    unsigned char xva[3], xvb[3];
#pragma unroll
    for (int e = 0; e < 3; e++) {
        int idx = t + 128 * e;
        int ii = (idx < 288) ? idx : 0;
        int ci = ii / 72, rem = ii - ci * 72;
        int rr = rem / 18, c = rem - rr * 18;
        int gi = i0 + rr, gj = j0 + c;
        xci_[e] = ci;
        xg_off[e] = gi * Hin + gj;
        xva[e] = (gi < Hin && gj < Hin);
        xvb[e] = (gi + 2 < Hin && gj < Hin);
    }

    float2 wreg2[9];
    float2 xreg[3];

    // ---- prologue: tile 0 to buffer 0, prefetch tile 1 ----
    {
        const float2* wp2 = (const float2*)(wg_base);
#pragma unroll
        for (int k = 0; k < 9; k++) wreg2[k] = __ldg(&wp2[k]);
#pragma unroll
        for (int e = 0; e < 3; e++) {
            const float* p = in + xci_[e] * Hin * Hin + xg_off[e];
            xreg[e].x = xva[e] ? __ldg(p) : 0.f;
            xreg[e].y = xvb[e] ? __ldg(p + 2 * Hin) : 0.f;
        }
    }
#pragma unroll
    for (int k = 0; k < 9; k++) {
        float2 v = wreg2[k];
        ws[0][wsbase + 2 * k]     = make_float2(v.x, v.x);
        ws[0][wsbase + 2 * k + 1] = make_float2(v.y, v.y);
    }
    xp[0][t] = xreg[0];
    xp[0][t + 128] = xreg[1];
    if (t < 32) xp[0][t + 256] = xreg[2];
    {
        const float2* wp2 = (const float2*)(wg_base + CI_T * 9);
#pragma unroll
        for (int k = 0; k < 9; k++) wreg2[k] = __ldg(&wp2[k]);
#pragma unroll
        for (int e = 0; e < 3; e++) {
            const float* p = in + (CI_T + xci_[e]) * Hin * Hin + xg_off[e];
            xreg[e].x = xva[e] ? __ldg(p) : 0.f;
            xreg[e].y = xvb[e] ? __ldg(p + 2 * Hin) : 0.f;
        }
    }
    __syncthreads();

    ull acc[2][8];
#pragma unroll
    for (int cr = 0; cr < 2; cr++) {
        float bv = b[zc + cogrp * 2 + cr];
        ull bp = pk(bv, bv);
#pragma unroll
        for (int c = 0; c < 8; c++) acc[cr][c] = bp;
    }

    for (int i = 0; i < NITER; i++) {
        int cur = i & 1, nxt = cur ^ 1;

        if (i + 1 < NITER) {
#pragma unroll
            for (int k = 0; k < 9; k++) {
                float2 v = wreg2[k];
                ws[nxt][wsbase + 2 * k]     = make_float2(v.x, v.x);
                ws[nxt][wsbase + 2 * k + 1] = make_float2(v.y, v.y);
            }
            xp[nxt][t] = xreg[0];
            xp[nxt][t + 128] = xreg[1];
            if (t < 32) xp[nxt][t + 256] = xreg[2];
        }
        if (i + 2 < NITER) {
            int nb = (i + 2) * CI_T;
            const float2* wp2 = (const float2*)(wg_base + nb * 9);
#pragma unroll
            for (int k = 0; k < 9; k++) wreg2[k] = __ldg(&wp2[k]);
#pragma unroll
            for (int e = 0; e < 3; e++) {
                const float* p = in + (nb + xci_[e]) * Hin * Hin + xg_off[e];
                xreg[e].x = xva[e] ? __ldg(p) : 0.f;
                xreg[e].y = xvb[e] ? __ldg(p + 2 * Hin) : 0.f;
            }
        }

        // compute from current buffer
#pragma unroll
        for (int ci = 0; ci < CI_T; ci++) {
#pragma unroll
            for (int di = 0; di < 3; di++) {
                const ulonglong2* xr =
                    (const ulonglong2*)&xp[cur][ci * 72 + (rp + di) * 18 + chh * 8];
                ulonglong2 q0 = xr[0];
                ulonglong2 q1 = xr[1];
                ulonglong2 q2 = xr[2];
                ulonglong2 q3 = xr[3];
                ulonglong2 q4 = xr[4];
                ull xv[10] = {q0.x, q0.y, q1.x, q1.y, q2.x,
                              q2.y, q3.x, q3.y, q4.x, q4.y};
#pragma unroll
                for (int dj = 0; dj < 3; dj++) {
#pragma unroll
                    for (int cr = 0; cr < 2; cr++) {
                        ull wp = *(const ull*)&ws[cur][(cogrp * 2 + cr) * WS_STRIDE
                                                      + ci * 9 + di * 3 + dj];
#pragma unroll
                        for (int c = 0; c < 8; c++)
                            fma2(acc[cr][c], wp, xv[dj + c]);
                    }
                }
            }
        }
        __syncthreads();
    }

    // write out: rows (i0+rp, i0+rp+2), cols j0+chh*8 .. +7
    int r0 = i0 + rp, r1 = i0 + rp + 2;
    int colb = j0 + chh * 8;
#pragma unroll
    for (int cr = 0; cr < 2; cr++) {
        long pb = (long)(zc + cogrp * 2 + cr) * Hout * Hout;
#pragma unroll
        for (int c = 0; c < 8; c++) {
            float2 v = up(acc[cr][c]);
            int col = colb + c;
            if (col < Hout) {
                if (r0 < Hout) out[pb + (long)r0 * Hout + col] = fmaxf(v.x, 0.f);
                if (r1 < Hout) out[pb + (long)r1 * Hout + col] = fmaxf(v.y, 0.f);
            }
        }
    }
}

// ---------------- kernel 4: GEMV partials (DRAM-bound, ~80% of peak) ----------------
__global__ void __launch_bounds__(256) gemv_kernel(
    const float* __restrict__ flat, const float* __restrict__ lw,
    float* __restrict__ part) {
    __shared__ __align__(16) float sx[GCHUNK];
    int bc = blockIdx.x;
    long base = (long)bc * GCHUNK;
    int n = FEAT - base;
    if (n > GCHUNK) n = GCHUNK;
    int n4 = n >> 2;

    const float4* xg  = (const float4*)(flat + base);
    float4*       sx4 = (float4*)sx;
    for (int k = threadIdx.x; k < n4; k += 256) sx4[k] = xg[k];
    __syncthreads();

    int wid  = threadIdx.x >> 5;
    int lane = threadIdx.x & 31;
    int rbase = blockIdx.y * 128 + wid * 16;

    for (int g = 0; g < 4; g++) {
        int o = rbase + g * 4;
        const float4* w0 = (const float4*)(lw + (size_t)(o + 0) * FEAT + base);
        const float4* w1 = (const float4*)(lw + (size_t)(o + 1) * FEAT + base);
        const float4* w2 = (const float4*)(lw + (size_t)(o + 2) * FEAT + base);
        const float4* w3 = (const float4*)(lw + (size_t)(o + 3) * FEAT + base);
        float s0 = 0.f, s1 = 0.f, s2 = 0.f, s3 = 0.f;
        for (int k = lane; k < n4; k += 128) {
            float4 a[4][4];
#pragma unroll
            for (int j = 0; j < 4; j++) {
                int kk = k + 32 * j;
                a[0][j] = __ldcs(&w0[kk]);
                a[1][j] = __ldcs(&w1[kk]);
                a[2][j] = __ldcs(&w2[kk]);
                a[3][j] = __ldcs(&w3[kk]);
            }
#pragma unroll
            for (int j = 0; j < 4; j++) {
                float4 xv = sx4[k + 32 * j];
                s0 = fmaf(a[0][j].x, xv.x, s0); s0 = fmaf(a[0][j].y, xv.y, s0);
                s0 = fmaf(a[0][j].z, xv.z, s0); s0 = fmaf(a[0][j].w, xv.w, s0);
                s1 = fmaf(a[1][j].x, xv.x, s1); s1 = fmaf(a[1][j].y, xv.y, s1);
                s1 = fmaf(a[1][j].z, xv.z, s1); s1 = fmaf(a[1][j].w, xv.w, s1);
                s2 = fmaf(a[2][j].x, xv.x, s2); s2 = fmaf(a[2][j].y, xv.y, s2);
                s2 = fmaf(a[2][j].z, xv.z, s2); s2 = fmaf(a[2][j].w, xv.w, s2);
                s3 = fmaf(a[3][j].x, xv.x, s3); s3 = fmaf(a[3][j].y, xv.y, s3);
                s3 = fmaf(a[3][j].z, xv.z, s3); s3 = fmaf(a[3][j].w, xv.w, s3);
            }
        }
#pragma unroll
        for (int off = 16; off; off >>= 1) {
            s0 += __shfl_xor_sync(0xffffffffu, s0, off);
            s1 += __shfl_xor_sync(0xffffffffu, s1, off);
            s2 += __shfl_xor_sync(0xffffffffu, s2, off);
            s3 += __shfl_xor_sync(0xffffffffu, s3, off);
        }
        if (lane == 0) {
            part[bc * OUTD + o + 0] = s0;
            part[bc * OUTD + o + 1] = s1;
            part[bc * OUTD + o + 2] = s2;
            part[bc * OUTD + o + 3] = s3;
        }
    }
}

// ---------------- kernel 5: parallel deterministic reduce + bias ----------------
__global__ void reduce_kernel(const float* __restrict__ part,
                              const float* __restrict__ lb,
                              float* __restrict__ out) {
    int o = blockIdx.x * 8 + (threadIdx.x >> 5);
    int lane = threadIdx.x & 31;
    float s = 0.f;
    for (int c = lane; c < NBLK; c += 32) s += part[c * OUTD + o];
#pragma unroll
    for (int off = 16; off; off >>= 1)
        s += __shfl_xor_sync(0xffffffffu, s, off);
    if (lane == 0) out[o] = lb[o] + s;
}

// ---------------- launch (single stream, full z=2 convs) ----------------
extern "C" void kernel_launch(void* const* d_in, const int* in_sizes, int n_in,
                              void* d_out, int out_size) {
    const int*   x      = (const int*)  d_in[0];
    const float* cat_w  = (const float*)d_in[1];
    const float* cat_b  = (const float*)d_in[2];
    const float* conv_w = (const float*)d_in[3];
    const float* conv_b = (const float*)d_in[4];
    const float* lin_w  = (const float*)d_in[5];
    const float* lin_b  = (const float*)d_in[6];
    float* out = (float*)d_out;

    float *y0, *y1, *y2, *part;
    cudaGetSymbolAddress((void**)&y0,   g_y0);
    cudaGetSymbolAddress((void**)&y1,   g_y1);
    cudaGetSymbolAddress((void**)&y2,   g_y2);
    cudaGetSymbolAddress((void**)&part, g_part);

    dim3 gA((H0 * H0 + 127) / 128, NPC);
    piece_conv<<<gA, 128>>>(x, cat_w, cat_b, y0);

    dim3 g1((H1 + 15) / 16, (H1 + 3) / 4, 2);
    conv3x3<<<g1, 128>>>(y0, conv_w, conv_b, y1, H0, H1);

    dim3 g2((H2 + 15) / 16, (H2 + 3) / 4, 2);
    conv3x3<<<g2, 128>>>(y1, conv_w, conv_b, y2, H1, H2);

    dim3 gg(NBLK, 2);
    gemv_kernel<<<gg, 256>>>(y2, lin_w, part);
    reduce_kernel<<<32, 256>>>(part, lin_b, out);
}

// round 15
// speedup vs baseline: 1.0197x; 1.0197x over previous
#include <cuda_runtime.h>

// ---------------- problem constants ----------------
#define NPC   16
#define FBP   8
#define CH    128
#define HH    96
#define H0    94          // after piece conv
#define H1    92          // after conv #1
#define H2    90          // after conv #2
#define FEAT  (CH*H2*H2)  // 1,036,800
#define OUTD  256
#define GCHUNK 4096
#define NBLK  ((FEAT + GCHUNK - 1) / GCHUNK)   // 254

typedef unsigned long long ull;

// ---------------- scratch (no allocation allowed) ----------------
__device__ float g_y0[CH * H0 * H0];
__device__ float g_y1[CH * H1 * H1];
__device__ float g_y2[CH * H2 * H2];
__device__ float g_part[NBLK * OUTD];

// ---------------- packed f32x2 helpers (sm_103a) ----------------
__device__ __forceinline__ ull pk(float lo, float hi) {
    ull r;
    asm("mov.b64 %0, {%1, %2};" : "=l"(r) : "f"(lo), "f"(hi));
    return r;
}
__device__ __forceinline__ void fma2(ull &d, ull a, ull b) {
    asm("fma.rn.f32x2 %0, %1, %2, %0;" : "+l"(d) : "l"(a), "l"(b));
}
__device__ __forceinline__ float2 up(ull v) {
    float x, y;
    asm("mov.b64 {%0, %1}, %2;" : "=f"(x), "=f"(y) : "l"(v));
    return make_float2(x, y);
}

// ---------------- kernel 1: grouped piece conv + bias + relu ----------------
__global__ void piece_conv(const int* __restrict__ x, const float* __restrict__ cw,
                           const float* __restrict__ cb, float* __restrict__ y0) {
    __shared__ float sw[72];
    __shared__ float sb[8];
    int p = blockIdx.y;
    if (threadIdx.x < 72) sw[threadIdx.x] = cw[p * 72 + threadIdx.x];
    if (threadIdx.x < 8)  sb[threadIdx.x] = cb[p * 8 + threadIdx.x];
    __syncthreads();
    int pix = blockIdx.x * blockDim.x + threadIdx.x;
    if (pix >= H0 * H0) return;
    int i = pix / H0, j = pix % H0;
    float acc[FBP];
#pragma unroll
    for (int f = 0; f < FBP; f++) acc[f] = sb[f];
#pragma unroll
    for (int di = 0; di < 3; di++) {
#pragma unroll
        for (int dj = 0; dj < 3; dj++) {
            int v = x[(i + di) * HH + (j + dj)];
            if (v == p) {
#pragma unroll
                for (int f = 0; f < FBP; f++) acc[f] += sw[f * 9 + di * 3 + dj];
            }
        }
    }
#pragma unroll
    for (int f = 0; f < FBP; f++)
        y0[(p * FBP + f) * (H0 * H0) + pix] = fmaxf(acc[f], 0.f);
}

// ---------------- conv 3x3 VALID + bias + relu ----------------
// 128 threads/block, 64 Cout per block (z selects half), tile 4 rows x 16 cols.
// Thread = 2 Cout x 1 rowpair x 8 col-f32x2 (32 acc regs).
// Each weight LDS.64 feeds 8 FMA2; each (ci,di) x read = 5 LDS.128 feeds 48.
// Double-buffered SMEM, one __syncthreads per cib iteration; register
// prefetch of tile i+2 flies under the FMA2 phase.
// __launch_bounds__(128,3): 170-reg budget -> NO SPILLS (the (128,4) cap
// forced 128 regs and spilled the accumulators; that was R12/R14's regression).
#define CI_T 4
#define NITER (CH / CI_T)   // 32
#define WS_STRIDE 37
__global__ void __launch_bounds__(128, 3) conv3x3(
    const float* __restrict__ in, const float* __restrict__ w,
    const float* __restrict__ b, float* __restrict__ out,
    int Hin, int Hout) {
    __shared__ __align__(16) float2 ws[2][64 * WS_STRIDE];
    __shared__ __align__(16) float2 xp[2][CI_T * 4 * 18];   // 288 entries

    int t = threadIdx.x;
    int cogrp = t >> 2;               // 0..31, 2 Cout each
    int pg    = t & 3;
    int rp    = pg & 1;               // rowpair: rows (rp, rp+2)
    int chh   = pg >> 1;              // col half: cols chh*8 .. +7 (f32x2 units)
    int i0 = blockIdx.y * 4, j0 = blockIdx.x * 16;
    int zc = blockIdx.z * 64;

    // weight staging: thread stages row lc = t>>1, scalars r0..r0+17 (contiguous)
    int lc_s = t >> 1;
    int r0_s = (t & 1) * 18;
    const float* wg_base = w + (size_t)(zc + lc_s) * (CH * 9) + r0_s;
    int wsbase = lc_s * WS_STRIDE + r0_s;

    // x staging maps: 288 entries, thread covers t, t+128, (t<32) t+256
    int xg_off[3], xci_[3];
    unsigned char xva[3], xvb[3];
#pragma unroll
    for (int e = 0; e < 3; e++) {
        int idx = t + 128 * e;
        int ii = (idx < 288) ? idx : 0;
        int ci = ii / 72, rem = ii - ci * 72;
        int rr = rem / 18, c = rem - rr * 18;
        int gi = i0 + rr, gj = j0 + c;
        xci_[e] = ci;
        xg_off[e] = gi * Hin + gj;
        xva[e] = (gi < Hin && gj < Hin);
        xvb[e] = (gi + 2 < Hin && gj < Hin);
    }

    float2 wreg2[9];
    float2 xreg[3];

    // ---- prologue: tile 0 to buffer 0, prefetch tile 1 ----
    {
        const float2* wp2 = (const float2*)(wg_base);
#pragma unroll
        for (int k = 0; k < 9; k++) wreg2[k] = __ldg(&wp2[k]);
#pragma unroll
        for (int e = 0; e < 3; e++) {
            const float* p = in + xci_[e] * Hin * Hin + xg_off[e];
            xreg[e].x = xva[e] ? __ldg(p) : 0.f;
            xreg[e].y = xvb[e] ? __ldg(p + 2 * Hin) : 0.f;
        }
    }
#pragma unroll
    for (int k = 0; k < 9; k++) {
        float2 v = wreg2[k];
        ws[0][wsbase + 2 * k]     = make_float2(v.x, v.x);
        ws[0][wsbase + 2 * k + 1] = make_float2(v.y, v.y);
    }
    xp[0][t] = xreg[0];
    xp[0][t + 128] = xreg[1];
    if (t < 32) xp[0][t + 256] = xreg[2];
    {
        const float2* wp2 = (const float2*)(wg_base + CI_T * 9);
#pragma unroll
        for (int k = 0; k < 9; k++) wreg2[k] = __ldg(&wp2[k]);
#pragma unroll
        for (int e = 0; e < 3; e++) {
            const float* p = in + (CI_T + xci_[e]) * Hin * Hin + xg_off[e];
            xreg[e].x = xva[e] ? __ldg(p) : 0.f;
            xreg[e].y = xvb[e] ? __ldg(p + 2 * Hin) : 0.f;
        }
    }
    __syncthreads();

    ull acc[2][8];
#pragma unroll
    for (int cr = 0; cr < 2; cr++) {
        float bv = b[zc + cogrp * 2 + cr];
        ull bp = pk(bv, bv);
#pragma unroll
        for (int c = 0; c < 8; c++) acc[cr][c] = bp;
    }

    for (int i = 0; i < NITER; i++) {
        int cur = i & 1, nxt = cur ^ 1;

        if (i + 1 < NITER) {
#pragma unroll
            for (int k = 0; k < 9; k++) {
                float2 v = wreg2[k];
                ws[nxt][wsbase + 2 * k]     = make_float2(v.x, v.x);
                ws[nxt][wsbase + 2 * k + 1] = make_float2(v.y, v.y);
            }
            xp[nxt][t] = xreg[0];
            xp[nxt][t + 128] = xreg[1];
            if (t < 32) xp[nxt][t + 256] = xreg[2];
        }
        if (i + 2 < NITER) {
            int nb = (i + 2) * CI_T;
            const float2* wp2 = (const float2*)(wg_base + nb * 9);
#pragma unroll
            for (int k = 0; k < 9; k++) wreg2[k] = __ldg(&wp2[k]);
#pragma unroll
            for (int e = 0; e < 3; e++) {
                const float* p = in + (nb + xci_[e]) * Hin * Hin + xg_off[e];
                xreg[e].x = xva[e] ? __ldg(p) : 0.f;
                xreg[e].y = xvb[e] ? __ldg(p + 2 * Hin) : 0.f;
            }
        }

        // compute from current buffer
#pragma unroll
        for (int ci = 0; ci < CI_T; ci++) {
#pragma unroll
            for (int di = 0; di < 3; di++) {
                const ulonglong2* xr =
                    (const ulonglong2*)&xp[cur][ci * 72 + (rp + di) * 18 + chh * 8];
                ulonglong2 q0 = xr[0];
                ulonglong2 q1 = xr[1];
                ulonglong2 q2 = xr[2];
                ulonglong2 q3 = xr[3];
                ulonglong2 q4 = xr[4];
                ull xv[10] = {q0.x, q0.y, q1.x, q1.y, q2.x,
                              q2.y, q3.x, q3.y, q4.x, q4.y};
#pragma unroll
                for (int dj = 0; dj < 3; dj++) {
#pragma unroll
                    for (int cr = 0; cr < 2; cr++) {
                        ull wp = *(const ull*)&ws[cur][(cogrp * 2 + cr) * WS_STRIDE
                                                      + ci * 9 + di * 3 + dj];
#pragma unroll
                        for (int c = 0; c < 8; c++)
                            fma2(acc[cr][c], wp, xv[dj + c]);
                    }
                }
            }
        }
        __syncthreads();
    }

    // write out: rows (i0+rp, i0+rp+2), cols j0+chh*8 .. +7
    int r0 = i0 + rp, r1 = i0 + rp + 2;
    int colb = j0 + chh * 8;
#pragma unroll
    for (int cr = 0; cr < 2; cr++) {
        long pb = (long)(zc + cogrp * 2 + cr) * Hout * Hout;
#pragma unroll
        for (int c = 0; c < 8; c++) {
            float2 v = up(acc[cr][c]);
            int col = colb + c;
            if (col < Hout) {
                if (r0 < Hout) out[pb + (long)r0 * Hout + col] = fmaxf(v.x, 0.f);
                if (r1 < Hout) out[pb + (long)r1 * Hout + col] = fmaxf(v.y, 0.f);
            }
        }
    }
}

// ---------------- kernel 4: GEMV partials (DRAM-bound) ----------------
// grid = (NBLK, 4): 1016 blocks, 64 rows per block, warp owns 8 rows
// (2 groups of 4). More co-resident blocks -> deeper LDG pipeline.
__global__ void __launch_bounds__(256) gemv_kernel(
    const float* __restrict__ flat, const float* __restrict__ lw,
    float* __restrict__ part) {
    __shared__ __align__(16) float sx[GCHUNK];
    int bc = blockIdx.x;
    long base = (long)bc * GCHUNK;
    int n = FEAT - base;
    if (n > GCHUNK) n = GCHUNK;
    int n4 = n >> 2;

    const float4* xg  = (const float4*)(flat + base);
    float4*       sx4 = (float4*)sx;
    for (int k = threadIdx.x; k < n4; k += 256) sx4[k] = xg[k];
    __syncthreads();

    int wid  = threadIdx.x >> 5;
    int lane = threadIdx.x & 31;
    int rbase = blockIdx.y * 64 + wid * 8;

    for (int g = 0; g < 2; g++) {
        int o = rbase + g * 4;
        const float4* w0 = (const float4*)(lw + (size_t)(o + 0) * FEAT + base);
        const float4* w1 = (const float4*)(lw + (size_t)(o + 1) * FEAT + base);
        const float4* w2 = (const float4*)(lw + (size_t)(o + 2) * FEAT + base);
        const float4* w3 = (const float4*)(lw + (size_t)(o + 3) * FEAT + base);
        float s0 = 0.f, s1 = 0.f, s2 = 0.f, s3 = 0.f;
        for (int k = lane; k < n4; k += 128) {
            float4 a[4][4];
#pragma unroll
            for (int j = 0; j < 4; j++) {
                int kk = k + 32 * j;
                a[0][j] = __ldcs(&w0[kk]);
                a[1][j] = __ldcs(&w1[kk]);
                a[2][j] = __ldcs(&w2[kk]);
                a[3][j] = __ldcs(&w3[kk]);
            }
#pragma unroll
            for (int j = 0; j < 4; j++) {
                float4 xv = sx4[k + 32 * j];
                s0 = fmaf(a[0][j].x, xv.x, s0); s0 = fmaf(a[0][j].y, xv.y, s0);
                s0 = fmaf(a[0][j].z, xv.z, s0); s0 = fmaf(a[0][j].w, xv.w, s0);
                s1 = fmaf(a[1][j].x, xv.x, s1); s1 = fmaf(a[1][j].y, xv.y, s1);
                s1 = fmaf(a[1][j].z, xv.z, s1); s1 = fmaf(a[1][j].w, xv.w, s1);
                s2 = fmaf(a[2][j].x, xv.x, s2); s2 = fmaf(a[2][j].y, xv.y, s2);
                s2 = fmaf(a[2][j].z, xv.z, s2); s2 = fmaf(a[2][j].w, xv.w, s2);
                s3 = fmaf(a[3][j].x, xv.x, s3); s3 = fmaf(a[3][j].y, xv.y, s3);
                s3 = fmaf(a[3][j].z, xv.z, s3); s3 = fmaf(a[3][j].w, xv.w, s3);
            }
        }
#pragma unroll
        for (int off = 16; off; off >>= 1) {
            s0 += __shfl_xor_sync(0xffffffffu, s0, off);
            s1 += __shfl_xor_sync(0xffffffffu, s1, off);
            s2 += __shfl_xor_sync(0xffffffffu, s2, off);
            s3 += __shfl_xor_sync(0xffffffffu, s3, off);
        }
        if (lane == 0) {
            part[bc * OUTD + o + 0] = s0;
            part[bc * OUTD + o + 1] = s1;
            part[bc * OUTD + o + 2] = s2;
            part[bc * OUTD + o + 3] = s3;
        }
    }
}

// ---------------- kernel 5: parallel deterministic reduce + bias ----------------
__global__ void reduce_kernel(const float* __restrict__ part,
                              const float* __restrict__ lb,
                              float* __restrict__ out) {
    int o = blockIdx.x * 8 + (threadIdx.x >> 5);
    int lane = threadIdx.x & 31;
    float s = 0.f;
    for (int c = lane; c < NBLK; c += 32) s += part[c * OUTD + o];
#pragma unroll
    for (int off = 16; off; off >>= 1)
        s += __shfl_xor_sync(0xffffffffu, s, off);
    if (lane == 0) out[o] = lb[o] + s;
}

// ---------------- launch (single stream, full z=2 convs) ----------------
extern "C" void kernel_launch(void* const* d_in, const int* in_sizes, int n_in,
                              void* d_out, int out_size) {
    const int*   x      = (const int*)  d_in[0];
    const float* cat_w  = (const float*)d_in[1];
    const float* cat_b  = (const float*)d_in[2];
    const float* conv_w = (const float*)d_in[3];
    const float* conv_b = (const float*)d_in[4];
    const float* lin_w  = (const float*)d_in[5];
    const float* lin_b  = (const float*)d_in[6];
    float* out = (float*)d_out;

    float *y0, *y1, *y2, *part;
    cudaGetSymbolAddress((void**)&y0,   g_y0);
    cudaGetSymbolAddress((void**)&y1,   g_y1);
    cudaGetSymbolAddress((void**)&y2,   g_y2);
    cudaGetSymbolAddress((void**)&part, g_part);

    dim3 gA((H0 * H0 + 127) / 128, NPC);
    piece_conv<<<gA, 128>>>(x, cat_w, cat_b, y0);

    dim3 g1((H1 + 15) / 16, (H1 + 3) / 4, 2);
    conv3x3<<<g1, 128>>>(y0, conv_w, conv_b, y1, H0, H1);

    dim3 g2((H2 + 15) / 16, (H2 + 3) / 4, 2);
    conv3x3<<<g2, 128>>>(y1, conv_w, conv_b, y2, H1, H2);

    dim3 gg(NBLK, 4);
    gemv_kernel<<<gg, 256>>>(y2, lin_w, part);
    reduce_kernel<<<32, 256>>>(part, lin_b, out);
}